// round 4
// baseline (speedup 1.0000x reference)
#include <cuda_runtime.h>
#include <cuda_bf16.h>
#include <stdint.h>

#define N_NODES 100000
#define N_EDGES 1600000
#define HID 128
#define OUTD 64

// ---------------- static device scratch (no allocations allowed) ----------
__device__ int   g_deg[N_NODES];
__device__ float g_dinv[N_NODES];
__device__ int   g_ptr[N_NODES + 1];
__device__ int   g_fill[N_NODES];
__device__ int   g_is64;                                      // edge dtype flag
__device__ __align__(16) unsigned long long g_edges[N_EDGES]; // {norm<<32 | col}
__device__ __align__(16) float g_ya[N_NODES * OUTD];
__device__ __align__(16) float g_yb[N_NODES * OUTD];
__device__ __align__(16) float g_acc[N_NODES * OUTD];

// ---------------- dtype detection (device-side, graph-capturable) ---------
// If the buffer is true int64, every value is a node id < N_NODES.
// If it is int32 read as int64, the high 32 bits hold the NEXT index and are
// nonzero with probability ~1 per sample -> any huge value = int32 data.
__global__ void k_detect(const unsigned long long* __restrict__ p) {
    __shared__ int big;
    if (threadIdx.x == 0) big = 0;
    __syncthreads();
    for (int i = threadIdx.x; i < 2048; i += blockDim.x)
        if (p[i] >= (unsigned long long)N_NODES) big = 1;
    __syncthreads();
    if (threadIdx.x == 0) g_is64 = big ? 0 : 1;
}

// ---------------- build: degree histogram --------------------------------
__global__ void k_zero_deg() {
    int i = blockIdx.x * blockDim.x + threadIdx.x;
    if (i < N_NODES) g_deg[i] = 0;
}

__global__ void k_hist(const void* __restrict__ eiv) {
    int e = blockIdx.x * blockDim.x + threadIdx.x;
    if (e >= N_EDGES) return;
    int r = g_is64 ? (int)((const long long*)eiv)[e]
                   : ((const int*)eiv)[e];
    if (r >= 0 && r < N_NODES) atomicAdd(&g_deg[r], 1);
}

__global__ void k_dinv() {
    int i = blockIdx.x * blockDim.x + threadIdx.x;
    if (i < N_NODES) {
        int d = g_deg[i];
        float df = (float)(d < 1 ? 1 : d);
        g_dinv[i] = rsqrtf(df);
    }
}

// ---------------- build: 1-block exclusive scan -> csr ptr + fill cursors -
__global__ void k_scan() {
    __shared__ int sums[1024];
    const int t = threadIdx.x;
    const int chunk = (N_NODES + 1023) / 1024;
    int s0 = t * chunk;
    int s1 = s0 + chunk; if (s1 > N_NODES) s1 = N_NODES;
    if (s0 > N_NODES) s0 = N_NODES;

    int s = 0;
    for (int i = s0; i < s1; i++) s += g_deg[i];
    sums[t] = s;
    __syncthreads();
    for (int off = 1; off < 1024; off <<= 1) {
        int v = (t >= off) ? sums[t - off] : 0;
        __syncthreads();
        sums[t] += v;
        __syncthreads();
    }
    int base = (t == 0) ? 0 : sums[t - 1];
    for (int i = s0; i < s1; i++) {
        g_ptr[i]  = base;
        g_fill[i] = base;
        base += g_deg[i];
    }
    if (t == 1023) g_ptr[N_NODES] = sums[1023];
}

// ---------------- build: scatter edges into CSR buckets -------------------
__global__ void k_scatter(const void* __restrict__ eiv) {
    int e = blockIdx.x * blockDim.x + threadIdx.x;
    if (e >= N_EDGES) return;
    int r, c;
    if (g_is64) {
        r = (int)((const long long*)eiv)[e];
        c = (int)((const long long*)eiv)[N_EDGES + e];
    } else {
        r = ((const int*)eiv)[e];
        c = ((const int*)eiv)[N_EDGES + e];
    }
    if (r < 0 || r >= N_NODES || c < 0 || c >= N_NODES) return;
    float w = g_dinv[r] * g_dinv[c];
    int slot = atomicAdd(&g_fill[r], 1);
    g_edges[slot] = ((unsigned long long)__float_as_uint(w) << 32) |
                    (unsigned long long)(unsigned)c;
}

// ---------------- y0 = x @ W^T ; acc = y0 ---------------------------------
// Block = 128 threads = 4 warps; warp w owns outputs [16w, 16w+16).
// Lane pairs (l, l+16) split the 128-dim reduction; combine with one shfl.
__global__ void __launch_bounds__(128) k_gemm(const float* __restrict__ x,
                                              const float* __restrict__ W) {
    const int warp  = threadIdx.x >> 5;
    const int lane  = threadIdx.x & 31;
    const int o     = warp * 16 + (lane & 15);
    const int khalf = lane >> 4;          // 0 or 1

    float4 wr[16];
    const float4* Wv = (const float4*)(W + o * HID + khalf * 64);
#pragma unroll
    for (int i = 0; i < 16; i++) wr[i] = Wv[i];

    for (int v = blockIdx.x; v < N_NODES; v += gridDim.x) {
        const float4* xv = (const float4*)(x + v * HID + khalf * 64);
        float ax = 0.f, ay = 0.f, az = 0.f, aw = 0.f;
#pragma unroll
        for (int i = 0; i < 16; i++) {
            float4 xi = xv[i];
            ax += xi.x * wr[i].x;
            ay += xi.y * wr[i].y;
            az += xi.z * wr[i].z;
            aw += xi.w * wr[i].w;
        }
        float s = (ax + ay) + (az + aw);
        s += __shfl_down_sync(0xffffffffu, s, 16);
        if (khalf == 0) {
            g_ya[v * OUTD + o]  = s;
            g_acc[v * OUTD + o] = s;
        }
    }
}

// ---------------- propagate (middle layers): dst = P(src); acc += dst -----
// DIR==0: src=g_ya, dst=g_yb.  DIR==1: src=g_yb, dst=g_ya.
// 16 threads per node, one float4 per lane (covers 64 dims).
template <int DIR>
__global__ void __launch_bounds__(256) k_prop_mid() {
    const float* __restrict__ src = (DIR == 0) ? g_ya : g_yb;
    float*       __restrict__ dst = (DIR == 0) ? g_yb : g_ya;
    int gid = blockIdx.x * blockDim.x + threadIdx.x;
    int v = gid >> 4;
    int l = gid & 15;
    if (v >= N_NODES) return;
    int beg = g_ptr[v], end = g_ptr[v + 1];
    float ax = 0.f, ay = 0.f, az = 0.f, aw = 0.f;
    for (int e = beg; e < end; e++) {
        unsigned long long p = g_edges[e];
        int   c = (int)(unsigned)(p & 0xffffffffull);
        float w = __uint_as_float((unsigned)(p >> 32));
        float4 yv = *(const float4*)(src + c * OUTD + l * 4);
        ax += w * yv.x; ay += w * yv.y; az += w * yv.z; aw += w * yv.w;
    }
    int idx = v * OUTD + l * 4;
    float4 r; r.x = ax; r.y = ay; r.z = az; r.w = aw;
    *(float4*)(dst + idx) = r;
    float4 ac = *(const float4*)(g_acc + idx);
    ac.x += ax; ac.y += ay; ac.z += az; ac.w += aw;
    *(float4*)(g_acc + idx) = ac;
}

// ---------------- last propagate, fused epilogue --------------------------
// out = (acc + P(g_ya)) * 0.25 + b       (after 2 mid layers, src is g_ya)
__global__ void __launch_bounds__(256) k_prop_final(const float* __restrict__ bvec,
                                                    float* __restrict__ out) {
    const float* __restrict__ src = g_ya;
    int gid = blockIdx.x * blockDim.x + threadIdx.x;
    int v = gid >> 4;
    int l = gid & 15;
    if (v >= N_NODES) return;
    int beg = g_ptr[v], end = g_ptr[v + 1];
    float ax = 0.f, ay = 0.f, az = 0.f, aw = 0.f;
    for (int e = beg; e < end; e++) {
        unsigned long long p = g_edges[e];
        int   c = (int)(unsigned)(p & 0xffffffffull);
        float w = __uint_as_float((unsigned)(p >> 32));
        float4 yv = *(const float4*)(src + c * OUTD + l * 4);
        ax += w * yv.x; ay += w * yv.y; az += w * yv.z; aw += w * yv.w;
    }
    int idx = v * OUTD + l * 4;
    float4 ac = *(const float4*)(g_acc + idx);
    float b0 = bvec[l * 4 + 0], b1 = bvec[l * 4 + 1];
    float b2 = bvec[l * 4 + 2], b3 = bvec[l * 4 + 3];
    float4 r;
    r.x = (ac.x + ax) * 0.25f + b0;
    r.y = (ac.y + ay) * 0.25f + b1;
    r.z = (ac.z + az) * 0.25f + b2;
    r.w = (ac.w + aw) * 0.25f + b3;
    *(float4*)(out + idx) = r;
}

// ---------------- launcher ------------------------------------------------
extern "C" void kernel_launch(void* const* d_in, const int* in_sizes, int n_in,
                              void* d_out, int out_size) {
    // Identify inputs BY ELEMENT COUNT (robust to ordering). Counts:
    //   x: 12,800,000   W: 8,192   b: 64   edge_index: 3,200,000 (any dtype)
    const float* x = nullptr;
    const float* W = nullptr;
    const float* b = nullptr;
    const void*  ei = nullptr;
    for (int i = 0; i < n_in; i++) {
        long long s = in_sizes[i];
        if      (s == (long long)N_NODES * HID) x = (const float*)d_in[i];
        else if (s == (long long)OUTD * HID)    W = (const float*)d_in[i];
        else if (s == (long long)OUTD)          b = (const float*)d_in[i];
        else ei = d_in[i];
    }
    if (!x)  x  = (const float*)d_in[0];
    if (!ei) ei = d_in[1];
    if (!W)  W  = (const float*)d_in[2];
    if (!b)  b  = (const float*)d_in[3];

    float* out = (float*)d_out;

    const int TB = 256;
    const int eb = (N_EDGES + TB - 1) / TB;      // 6250
    const int nb = (N_NODES + TB - 1) / TB;      // 391
    const int pb = (N_NODES * 16 + TB - 1) / TB; // 6250

    // dtype probe (device-side; int64 vs int32 cannot be told apart by size)
    k_detect<<<1, 256>>>((const unsigned long long*)ei);

    // CSR build
    k_zero_deg<<<nb, TB>>>();
    k_hist<<<eb, TB>>>(ei);
    k_dinv<<<nb, TB>>>();
    k_scan<<<1, 1024>>>();
    k_scatter<<<eb, TB>>>(ei);

    // y0 = x @ W^T (projection first: propagation commutes with W)
    k_gemm<<<4096, 128>>>(x, W);

    // 3 propagation layers in 64-dim space
    k_prop_mid<0><<<pb, TB>>>();      // y1 = P(ya) -> yb, acc += y1
    k_prop_mid<1><<<pb, TB>>>();      // y2 = P(yb) -> ya, acc += y2
    k_prop_final<<<pb, TB>>>(b, out); // out = (acc + P(ya))/4 + b
}

// round 5
// speedup vs baseline: 1.3780x; 1.3780x over previous
#include <cuda_runtime.h>
#include <cuda_bf16.h>
#include <stdint.h>

#define N_NODES 100000
#define N_EDGES 1600000
#define HID 128
#define OUTD 64

// ---------------- static device scratch (no allocations allowed) ----------
__device__ int   g_deg[N_NODES];
__device__ float g_dinv[N_NODES];
__device__ int   g_ptr[N_NODES + 1];
__device__ int   g_fill[N_NODES];
__device__ int   g_is64;                                      // edge dtype flag
__device__ __align__(16) unsigned long long g_edges[N_EDGES]; // {norm<<32 | col}
__device__ __align__(16) float g_y0[N_NODES * OUTD];
__device__ __align__(16) float g_y1[N_NODES * OUTD];
__device__ __align__(16) float g_y2[N_NODES * OUTD];

// ---------------- dtype detection (device-side, graph-capturable) ---------
// True int64 edge data: every sampled 8-byte value is a node id < N_NODES.
// int32 data read as int64: high word holds the next index -> huge values.
__global__ void k_detect(const unsigned long long* __restrict__ p) {
    __shared__ int big;
    if (threadIdx.x == 0) big = 0;
    __syncthreads();
    for (int i = threadIdx.x; i < 2048; i += blockDim.x)
        if (p[i] >= (unsigned long long)N_NODES) big = 1;
    __syncthreads();
    if (threadIdx.x == 0) g_is64 = big ? 0 : 1;
}

// ---------------- build: degree histogram --------------------------------
__global__ void k_zero_deg() {
    int i = blockIdx.x * blockDim.x + threadIdx.x;
    if (i < N_NODES) g_deg[i] = 0;
}

__global__ void k_hist(const void* __restrict__ eiv) {
    int e = blockIdx.x * blockDim.x + threadIdx.x;
    if (e >= N_EDGES) return;
    int r = g_is64 ? (int)((const long long*)eiv)[e]
                   : ((const int*)eiv)[e];
    if (r >= 0 && r < N_NODES) atomicAdd(&g_deg[r], 1);
}

__global__ void k_dinv() {
    int i = blockIdx.x * blockDim.x + threadIdx.x;
    if (i < N_NODES) {
        int d = g_deg[i];
        float df = (float)(d < 1 ? 1 : d);
        g_dinv[i] = rsqrtf(df);
    }
}

// ---------------- build: 1-block exclusive scan -> csr ptr + fill cursors -
__global__ void k_scan() {
    __shared__ int sums[1024];
    const int t = threadIdx.x;
    const int chunk = (N_NODES + 1023) / 1024;
    int s0 = t * chunk;
    int s1 = s0 + chunk; if (s1 > N_NODES) s1 = N_NODES;
    if (s0 > N_NODES) s0 = N_NODES;

    int s = 0;
    for (int i = s0; i < s1; i++) s += g_deg[i];
    sums[t] = s;
    __syncthreads();
    for (int off = 1; off < 1024; off <<= 1) {
        int v = (t >= off) ? sums[t - off] : 0;
        __syncthreads();
        sums[t] += v;
        __syncthreads();
    }
    int base = (t == 0) ? 0 : sums[t - 1];
    for (int i = s0; i < s1; i++) {
        g_ptr[i]  = base;
        g_fill[i] = base;
        base += g_deg[i];
    }
    if (t == 1023) g_ptr[N_NODES] = sums[1023];
}

// ---------------- build: scatter edges into CSR buckets -------------------
__global__ void k_scatter(const void* __restrict__ eiv) {
    int e = blockIdx.x * blockDim.x + threadIdx.x;
    if (e >= N_EDGES) return;
    int r, c;
    if (g_is64) {
        r = (int)((const long long*)eiv)[e];
        c = (int)((const long long*)eiv)[N_EDGES + e];
    } else {
        r = ((const int*)eiv)[e];
        c = ((const int*)eiv)[N_EDGES + e];
    }
    if (r < 0 || r >= N_NODES || c < 0 || c >= N_NODES) return;
    float w = g_dinv[r] * g_dinv[c];
    int slot = atomicAdd(&g_fill[r], 1);
    g_edges[slot] = ((unsigned long long)__float_as_uint(w) << 32) |
                    (unsigned long long)(unsigned)c;
}

// ---------------- y0 = x @ W^T (shared-staged x tile) ---------------------
// Block = 128 threads = 4 warps, one 16-node tile per block (6250 blocks).
// x tile is loaded coalesced into SMEM once; compute reads it as half-warp
// broadcasts. Row stride 136 words with the upper half at +68 words so the
// two distinct broadcast addresses of one LDS.128 hit disjoint banks.
#define GTILE 16
#define XROW 136   // padded row stride in floats
__global__ void __launch_bounds__(128) k_gemm(const float* __restrict__ x,
                                              const float* __restrict__ W) {
    __shared__ float sx[GTILE * XROW];   // 8.5 KB

    const int tid   = threadIdx.x;
    const int warp  = tid >> 5;
    const int lane  = tid & 31;
    const int o     = warp * 16 + (lane & 15);
    const int khalf = lane >> 4;          // 0 or 1

    float4 wr[16];
    const float4* Wv = (const float4*)(W + o * HID + khalf * 64);
#pragma unroll
    for (int i = 0; i < 16; i++) wr[i] = Wv[i];

    const int base = blockIdx.x * GTILE;          // grid is exactly 6250
    // cooperative coalesced load: 16 nodes * 32 float4 = 512 float4
    const float4* xg = (const float4*)(x + (long long)base * HID);
#pragma unroll
    for (int j = 0; j < 4; j++) {
        int f4 = tid + j * 128;                   // 0..511
        int t  = f4 >> 5;                         // node in tile
        int k  = f4 & 31;                         // float4 within row
        float4 v = xg[f4];
        int word = t * XROW + ((k < 16) ? (k * 4) : (68 + (k - 16) * 4));
        *(float4*)(sx + word) = v;
    }
    __syncthreads();

#pragma unroll 1
    for (int t = 0; t < GTILE; t++) {
        const float4* xv = (const float4*)(sx + t * XROW + khalf * 68);
        float ax = 0.f, ay = 0.f, az = 0.f, aw = 0.f;
#pragma unroll
        for (int i = 0; i < 16; i++) {
            float4 xi = xv[i];
            ax += xi.x * wr[i].x;
            ay += xi.y * wr[i].y;
            az += xi.z * wr[i].z;
            aw += xi.w * wr[i].w;
        }
        float s = (ax + ay) + (az + aw);
        s += __shfl_down_sync(0xffffffffu, s, 16);
        if (khalf == 0) g_y0[(base + t) * OUTD + o] = s;
    }
}

// ---------------- propagate: dst = P(src), unroll-4 gathers ---------------
// 16 threads per node, one float4 per lane. 4 independent gathers in flight
// per node-half (8 per warp) to cover L2 latency.
__device__ __forceinline__ void prop_accum(const float* __restrict__ src,
                                           int beg, int end, int l,
                                           float& ax, float& ay,
                                           float& az, float& aw) {
    int e = beg;
    for (; e + 4 <= end; e += 4) {
        unsigned long long p0 = __ldg(&g_edges[e]);
        unsigned long long p1 = __ldg(&g_edges[e + 1]);
        unsigned long long p2 = __ldg(&g_edges[e + 2]);
        unsigned long long p3 = __ldg(&g_edges[e + 3]);
        const float4 f0 = *(const float4*)(src + (int)(unsigned)(p0 & 0xffffffffull) * OUTD + l * 4);
        const float4 f1 = *(const float4*)(src + (int)(unsigned)(p1 & 0xffffffffull) * OUTD + l * 4);
        const float4 f2 = *(const float4*)(src + (int)(unsigned)(p2 & 0xffffffffull) * OUTD + l * 4);
        const float4 f3 = *(const float4*)(src + (int)(unsigned)(p3 & 0xffffffffull) * OUTD + l * 4);
        float w0 = __uint_as_float((unsigned)(p0 >> 32));
        float w1 = __uint_as_float((unsigned)(p1 >> 32));
        float w2 = __uint_as_float((unsigned)(p2 >> 32));
        float w3 = __uint_as_float((unsigned)(p3 >> 32));
        ax = fmaf(w0, f0.x, ax); ay = fmaf(w0, f0.y, ay);
        az = fmaf(w0, f0.z, az); aw = fmaf(w0, f0.w, aw);
        ax = fmaf(w1, f1.x, ax); ay = fmaf(w1, f1.y, ay);
        az = fmaf(w1, f1.z, az); aw = fmaf(w1, f1.w, aw);
        ax = fmaf(w2, f2.x, ax); ay = fmaf(w2, f2.y, ay);
        az = fmaf(w2, f2.z, az); aw = fmaf(w2, f2.w, aw);
        ax = fmaf(w3, f3.x, ax); ay = fmaf(w3, f3.y, ay);
        az = fmaf(w3, f3.z, az); aw = fmaf(w3, f3.w, aw);
    }
    for (; e < end; e++) {
        unsigned long long p = __ldg(&g_edges[e]);
        const float4 f = *(const float4*)(src + (int)(unsigned)(p & 0xffffffffull) * OUTD + l * 4);
        float w = __uint_as_float((unsigned)(p >> 32));
        ax = fmaf(w, f.x, ax); ay = fmaf(w, f.y, ay);
        az = fmaf(w, f.z, az); aw = fmaf(w, f.w, aw);
    }
}

// LAYER 0: y1 = P(y0)   LAYER 1: y2 = P(y1)
template <int LAYER>
__global__ void __launch_bounds__(256) k_prop_mid() {
    const float* __restrict__ src = (LAYER == 0) ? g_y0 : g_y1;
    float*       __restrict__ dst = (LAYER == 0) ? g_y1 : g_y2;
    int gid = blockIdx.x * blockDim.x + threadIdx.x;
    int v = gid >> 4;
    int l = gid & 15;
    if (v >= N_NODES) return;
    float ax = 0.f, ay = 0.f, az = 0.f, aw = 0.f;
    prop_accum(src, g_ptr[v], g_ptr[v + 1], l, ax, ay, az, aw);
    float4 r; r.x = ax; r.y = ay; r.z = az; r.w = aw;
    *(float4*)(dst + v * OUTD + l * 4) = r;
}

// final: out = (y0 + y1 + y2 + P(y2)) * 0.25 + b
__global__ void __launch_bounds__(256) k_prop_final(const float* __restrict__ bvec,
                                                    float* __restrict__ out) {
    int gid = blockIdx.x * blockDim.x + threadIdx.x;
    int v = gid >> 4;
    int l = gid & 15;
    if (v >= N_NODES) return;
    float ax = 0.f, ay = 0.f, az = 0.f, aw = 0.f;
    prop_accum(g_y2, g_ptr[v], g_ptr[v + 1], l, ax, ay, az, aw);
    int idx = v * OUTD + l * 4;
    float4 a0 = *(const float4*)(g_y0 + idx);
    float4 a1 = *(const float4*)(g_y1 + idx);
    float4 a2 = *(const float4*)(g_y2 + idx);
    float b0 = bvec[l * 4 + 0], b1 = bvec[l * 4 + 1];
    float b2 = bvec[l * 4 + 2], b3 = bvec[l * 4 + 3];
    float4 r;
    r.x = (a0.x + a1.x + a2.x + ax) * 0.25f + b0;
    r.y = (a0.y + a1.y + a2.y + ay) * 0.25f + b1;
    r.z = (a0.z + a1.z + a2.z + az) * 0.25f + b2;
    r.w = (a0.w + a1.w + a2.w + aw) * 0.25f + b3;
    *(float4*)(out + idx) = r;
}

// ---------------- launcher ------------------------------------------------
extern "C" void kernel_launch(void* const* d_in, const int* in_sizes, int n_in,
                              void* d_out, int out_size) {
    // Identify inputs BY ELEMENT COUNT (robust to ordering). Counts:
    //   x: 12,800,000   W: 8,192   b: 64   edge_index: 3,200,000 (any dtype)
    const float* x = nullptr;
    const float* W = nullptr;
    const float* b = nullptr;
    const void*  ei = nullptr;
    for (int i = 0; i < n_in; i++) {
        long long s = in_sizes[i];
        if      (s == (long long)N_NODES * HID) x = (const float*)d_in[i];
        else if (s == (long long)OUTD * HID)    W = (const float*)d_in[i];
        else if (s == (long long)OUTD)          b = (const float*)d_in[i];
        else ei = d_in[i];
    }
    if (!x)  x  = (const float*)d_in[0];
    if (!ei) ei = d_in[1];
    if (!W)  W  = (const float*)d_in[2];
    if (!b)  b  = (const float*)d_in[3];

    float* out = (float*)d_out;

    const int TB = 256;
    const int eb = (N_EDGES + TB - 1) / TB;      // 6250
    const int nb = (N_NODES + TB - 1) / TB;      // 391
    const int pb = (N_NODES * 16 + TB - 1) / TB; // 6250

    // dtype probe (device-side; int64 vs int32 cannot be told apart by size)
    k_detect<<<1, 256>>>((const unsigned long long*)ei);

    // CSR build
    k_zero_deg<<<nb, TB>>>();
    k_hist<<<eb, TB>>>(ei);
    k_dinv<<<nb, TB>>>();
    k_scan<<<1, 1024>>>();
    k_scatter<<<eb, TB>>>(ei);

    // y0 = x @ W^T (projection first: propagation commutes with W)
    k_gemm<<<N_NODES / GTILE, 128>>>(x, W);      // 6250 blocks

    // 3 propagation layers in 64-dim space
    k_prop_mid<0><<<pb, TB>>>();      // y1 = P(y0)
    k_prop_mid<1><<<pb, TB>>>();      // y2 = P(y1)
    k_prop_final<<<pb, TB>>>(b, out); // out = (y0+y1+y2+P(y2))/4 + b
}